// round 4
// baseline (speedup 1.0000x reference)
#include <cuda_runtime.h>
#include <cuda_bf16.h>

#define N_NODES 100000
#define DIM 128

// Scratch: inverse L2 norms per node (allocation-free rule -> __device__ global).
__device__ float g_invnorm[N_NODES];

// Kernel 1: one warp per row. 128 floats = 4 per lane (float4).
__global__ void invnorm_kernel(const float* __restrict__ h, int n) {
    int warp_id = (blockIdx.x * blockDim.x + threadIdx.x) >> 5;
    int lane = threadIdx.x & 31;
    if (warp_id >= n) return;

    const float4 v = reinterpret_cast<const float4*>(h + (size_t)warp_id * DIM)[lane];
    float s = v.x * v.x + v.y * v.y + v.z * v.z + v.w * v.w;
    #pragma unroll
    for (int off = 16; off > 0; off >>= 1)
        s += __shfl_xor_sync(0xFFFFFFFFu, s, off);

    if (lane == 0) {
        float norm = sqrtf(s);
        g_invnorm[warp_id] = 1.0f / fmaxf(norm, 1e-12f);
    }
}

// Kernel 2: one warp per edge. Each lane loads float4 from src row and dst row
// (coalesced 512B per row), FMA dot, butterfly reduce, scale by invnorm product.
__global__ void sddmm_cos_kernel(const float* __restrict__ h,
                                 const int* __restrict__ src,
                                 const int* __restrict__ dst,
                                 float* __restrict__ out, int e, int n) {
    int warp_id = (blockIdx.x * blockDim.x + threadIdx.x) >> 5;
    int lane = threadIdx.x & 31;
    if (warp_id >= e) return;

    // Defensive clamp: if index dtype assumption is wrong we want a finite
    // rel_err diagnostic, not an illegal memory access.
    int s_idx = __ldg(src + warp_id);
    int d_idx = __ldg(dst + warp_id);
    s_idx = min(max(s_idx, 0), n - 1);
    d_idx = min(max(d_idx, 0), n - 1);

    const float4 a = __ldg(reinterpret_cast<const float4*>(h + (size_t)s_idx * DIM) + lane);
    const float4 b = __ldg(reinterpret_cast<const float4*>(h + (size_t)d_idx * DIM) + lane);

    float acc = a.x * b.x;
    acc = fmaf(a.y, b.y, acc);
    acc = fmaf(a.z, b.z, acc);
    acc = fmaf(a.w, b.w, acc);

    #pragma unroll
    for (int off = 16; off > 0; off >>= 1)
        acc += __shfl_xor_sync(0xFFFFFFFFu, acc, off);

    if (lane == 0)
        out[warp_id] = acc * g_invnorm[s_idx] * g_invnorm[d_idx];
}

extern "C" void kernel_launch(void* const* d_in, const int* in_sizes, int n_in,
                              void* d_out, int out_size) {
    const float* h   = (const float*)d_in[0];
    const int*   src = (const int*)d_in[1];   // int32: JAX demotes int64 w/o x64
    const int*   dst = (const int*)d_in[2];
    float* out = (float*)d_out;

    int n = in_sizes[0] / DIM;     // 100000
    int e = in_sizes[1];           // 640000 (element count, dtype-independent)

    {   // Kernel 1: n warps, 8 warps / 256-thread block
        int blocks = (n + 7) / 8;
        invnorm_kernel<<<blocks, 256>>>(h, n);
    }
    {   // Kernel 2: e warps
        int blocks = (e + 7) / 8;
        sddmm_cos_kernel<<<blocks, 256>>>(h, src, dst, out, e, n);
    }
}

// round 6
// speedup vs baseline: 1.6119x; 1.6119x over previous
#include <cuda_runtime.h>
#include <cuda_fp16.h>
#include <cuda_bf16.h>

#define N_NODES 100000
#define DIM 128

// Normalized feature cache, fp16, 16B-aligned: 100000 rows * 256 B = 25.6 MB.
// Declared as uint4 to guarantee alignment for uint4 loads in the edge kernel.
__device__ uint4 g_hn[(size_t)N_NODES * DIM * 2 / 16];  // 1,600,000 uint4

// Kernel 1: one warp per row. Load 4 floats/lane, reduce sumsq, normalize,
// convert to fp16, store 8 B/lane (coalesced 256 B per row).
__global__ void normalize_fp16_kernel(const float* __restrict__ h, int n) {
    int row = (blockIdx.x * blockDim.x + threadIdx.x) >> 5;
    int lane = threadIdx.x & 31;
    if (row >= n) return;

    const float4 v = reinterpret_cast<const float4*>(h + (size_t)row * DIM)[lane];
    float s = v.x * v.x + v.y * v.y + v.z * v.z + v.w * v.w;
    #pragma unroll
    for (int off = 16; off > 0; off >>= 1)
        s += __shfl_xor_sync(0xFFFFFFFFu, s, off);

    float inv = 1.0f / fmaxf(sqrtf(s), 1e-12f);  // uniform across warp after reduce

    __half2 p0 = __floats2half2_rn(v.x * inv, v.y * inv);
    __half2 p1 = __floats2half2_rn(v.z * inv, v.w * inv);
    uint2 packed = make_uint2(*reinterpret_cast<unsigned*>(&p0),
                              *reinterpret_cast<unsigned*>(&p1));
    // row*256 bytes + lane*8 bytes
    reinterpret_cast<uint2*>(g_hn)[(size_t)row * 32 + lane] = packed;
}

// Helper: dot of 8 fp16 pairs held in two uint4's, accumulated in fp32.
__device__ __forceinline__ float dot8h(uint4 a, uint4 b) {
    float acc = 0.0f;
    #pragma unroll
    for (int w = 0; w < 4; w++) {
        unsigned ua = (&a.x)[w], ub = (&b.x)[w];
        __half2 ha = *reinterpret_cast<__half2*>(&ua);
        __half2 hb = *reinterpret_cast<__half2*>(&ub);
        float2 fa = __half22float2(ha);
        float2 fb = __half22float2(hb);
        acc = fmaf(fa.x, fb.x, acc);
        acc = fmaf(fa.y, fb.y, acc);
    }
    return acc;
}

// Kernel 2: two edges per warp, 16 lanes per edge. Each lane loads one uint4
// (16 B = 8 halves) from the src row and dst row (16 lanes cover the full
// 256 B row), fp32-accumulated dot, 4-step half-warp butterfly reduce.
__global__ void sddmm_cos_fp16_kernel(const int* __restrict__ src,
                                      const int* __restrict__ dst,
                                      float* __restrict__ out, int e, int n) {
    int warp_id = (blockIdx.x * blockDim.x + threadIdx.x) >> 5;
    int lane = threadIdx.x & 31;
    int half_id = lane >> 4;      // 0 or 1: which edge in this warp
    int l = lane & 15;            // lane within the 16-lane group

    int e_idx = warp_id * 2 + half_id;
    if (e_idx >= e) return;       // e is even (640000) -> whole warp exits together

    int s_idx = __ldg(src + e_idx);
    int d_idx = __ldg(dst + e_idx);
    s_idx = min(max(s_idx, 0), n - 1);
    d_idx = min(max(d_idx, 0), n - 1);

    // Row = 256 B = 16 uint4; lane l takes the l-th uint4.
    const uint4* base = g_hn;
    uint4 a = __ldg(base + (size_t)s_idx * 16 + l);
    uint4 b = __ldg(base + (size_t)d_idx * 16 + l);

    float acc = dot8h(a, b);

    #pragma unroll
    for (int off = 8; off > 0; off >>= 1)
        acc += __shfl_xor_sync(0xFFFFFFFFu, acc, off);

    if (l == 0)
        out[e_idx] = acc;
}

extern "C" void kernel_launch(void* const* d_in, const int* in_sizes, int n_in,
                              void* d_out, int out_size) {
    const float* h   = (const float*)d_in[0];
    const int*   src = (const int*)d_in[1];   // int32 (JAX demotes int64)
    const int*   dst = (const int*)d_in[2];
    float* out = (float*)d_out;

    int n = in_sizes[0] / DIM;     // 100000
    int e = in_sizes[1];           // 640000

    {   // Kernel 1: n warps, 8 warps / 256-thread block
        int blocks = (n + 7) / 8;
        normalize_fp16_kernel<<<blocks, 256>>>(h, n);
    }
    {   // Kernel 2: e/2 warps (2 edges per warp)
        int warps = (e + 1) / 2;
        int blocks = (warps + 7) / 8;
        sddmm_cos_fp16_kernel<<<blocks, 256>>>(src, dst, out, e, n);
    }
}

// round 7
// speedup vs baseline: 2.1259x; 1.3189x over previous
#include <cuda_runtime.h>
#include <cuda_fp16.h>
#include <cuda_bf16.h>

#define N_NODES 100000
#define DIM 128

// Normalized feature cache, fp16, 16B-aligned: 100000 rows * 256 B = 25.6 MB.
__device__ uint4 g_hn[(size_t)N_NODES * DIM * 2 / 16];  // 1,600,000 uint4

// Kernel 1: one warp per row. Load 4 floats/lane, reduce sumsq, normalize,
// convert to fp16, store 8 B/lane (coalesced 256 B per row).
__global__ void normalize_fp16_kernel(const float* __restrict__ h, int n) {
    int row = (blockIdx.x * blockDim.x + threadIdx.x) >> 5;
    int lane = threadIdx.x & 31;
    if (row >= n) return;

    const float4 v = reinterpret_cast<const float4*>(h + (size_t)row * DIM)[lane];
    float s = v.x * v.x + v.y * v.y + v.z * v.z + v.w * v.w;
    #pragma unroll
    for (int off = 16; off > 0; off >>= 1)
        s += __shfl_xor_sync(0xFFFFFFFFu, s, off);

    float inv = 1.0f / fmaxf(sqrtf(s), 1e-12f);  // uniform across warp after reduce

    __half2 p0 = __floats2half2_rn(v.x * inv, v.y * inv);
    __half2 p1 = __floats2half2_rn(v.z * inv, v.w * inv);
    uint2 packed = make_uint2(*reinterpret_cast<unsigned*>(&p0),
                              *reinterpret_cast<unsigned*>(&p1));
    reinterpret_cast<uint2*>(g_hn)[(size_t)row * 32 + lane] = packed;
}

// Dot of 8 fp16 pairs held in two uint4's, accumulated in fp32.
__device__ __forceinline__ float dot8h(uint4 a, uint4 b) {
    float acc = 0.0f;
    #pragma unroll
    for (int w = 0; w < 4; w++) {
        unsigned ua = (&a.x)[w], ub = (&b.x)[w];
        __half2 ha = *reinterpret_cast<__half2*>(&ua);
        __half2 hb = *reinterpret_cast<__half2*>(&ub);
        float2 fa = __half22float2(ha);
        float2 fb = __half22float2(hb);
        acc = fmaf(fa.x, fb.x, acc);
        acc = fmaf(fa.y, fb.y, acc);
    }
    return acc;
}

// Kernel 2: FOUR edges per warp, 8 lanes per edge, 2 uint4 per row per lane.
// Each LDG.128 covers exactly one 128B line per 8-lane group (4 lines/warp,
// no sector splitting). MLP per thread = 4 row loads + 1 index load.
__global__ void sddmm_cos_fp16_kernel(const int* __restrict__ src,
                                      const int* __restrict__ dst,
                                      float* __restrict__ out, int e, int n) {
    int warp_id = (blockIdx.x * blockDim.x + threadIdx.x) >> 5;
    int lane = threadIdx.x & 31;
    int g = lane >> 3;            // 0..3: edge within warp
    int l = lane & 7;             // 0..7: lane within the 8-lane group

    int e_idx = warp_id * 4 + g;
    if (e_idx >= e) return;       // e % 4 == 0 -> whole warp exits together

    int s_idx = __ldg(src + e_idx);
    int d_idx = __ldg(dst + e_idx);
    s_idx = min(max(s_idx, 0), n - 1);
    d_idx = min(max(d_idx, 0), n - 1);

    const uint4* a_row = g_hn + (size_t)s_idx * 16;
    const uint4* b_row = g_hn + (size_t)d_idx * 16;

    // Two full-line loads per row: uint4 [l] (bytes 0..127) and [8+l] (128..255).
    uint4 a0 = __ldg(a_row + l);
    uint4 a1 = __ldg(a_row + 8 + l);
    uint4 b0 = __ldg(b_row + l);
    uint4 b1 = __ldg(b_row + 8 + l);

    float acc = dot8h(a0, b0) + dot8h(a1, b1);

    #pragma unroll
    for (int off = 4; off > 0; off >>= 1)
        acc += __shfl_xor_sync(0xFFFFFFFFu, acc, off);

    if (l == 0)
        out[e_idx] = acc;
}

extern "C" void kernel_launch(void* const* d_in, const int* in_sizes, int n_in,
                              void* d_out, int out_size) {
    const float* h   = (const float*)d_in[0];
    const int*   src = (const int*)d_in[1];   // int32 (JAX demotes int64)
    const int*   dst = (const int*)d_in[2];
    float* out = (float*)d_out;

    int n = in_sizes[0] / DIM;     // 100000
    int e = in_sizes[1];           // 640000

    {   // Kernel 1: n warps, 8 warps / 256-thread block
        int blocks = (n + 7) / 8;
        normalize_fp16_kernel<<<blocks, 256>>>(h, n);
    }
    {   // Kernel 2: e/4 warps (4 edges per warp), 8 warps / block
        int warps = (e + 3) / 4;
        int blocks = (warps + 7) / 8;
        sddmm_cos_fp16_kernel<<<blocks, 256>>>(src, dst, out, e, n);
    }
}